// round 1
// baseline (speedup 1.0000x reference)
#include <cuda_runtime.h>
#include <cstdint>
#include <cstdio>
#include <cub/cub.cuh>

// Problem constants (from reference setup_inputs)
#define B_  8
#define N_  131072            // 2^17
#define M_  (B_ * N_)         // 1048576 points
#define C_  76

// ---------------- device scratch (no allocation allowed) ----------------
__device__ float               g_props[(size_t)M_ * 8];   // 32 MB  [x, ytop, z, h, w, l, ry, score]
__device__ unsigned long long  g_keys[M_];                // 8 MB
__device__ unsigned long long  g_keys_alt[M_];            // 8 MB
__device__ unsigned int        g_vals[M_];                // 4 MB
__device__ unsigned int        g_vals_alt[M_];            // 4 MB
__device__ unsigned char       g_temp[32u << 20];         // 32 MB cub temp

// ---------------- decode: warp per point ----------------
// reg layout per point (76 floats):
//  [0:12)  x bins     [12:24) z bins    [24:36) x res    [36:48) z res
//  [48]    y offset   [49:61) ry bins   [61:73) ry res   [73:76) hwl
__global__ void decode_kernel(const float* __restrict__ scores,
                              const float* __restrict__ reg,
                              const float* __restrict__ xyz,
                              const float* __restrict__ anchor)
{
    const unsigned FULL = 0xffffffffu;
    const int gw   = (blockIdx.x * blockDim.x + threadIdx.x) >> 5;
    const int lane = threadIdx.x & 31;
    if (gw >= M_) return;

    const float* r = reg + (size_t)gw * C_;
    // 3 coalesced loads cover the 76 floats
    const float a  = r[lane];                              // idx 0..31
    const float bv = r[32 + lane];                         // idx 32..63
    const float cv = (lane < 12) ? r[64 + lane] : 0.0f;    // idx 64..75

    const float NEG = -3.4e38f;
    float v; int idx;

    // x_bin = argmax reg[0:12]  (first-max tiebreak: lower idx)
    v = (lane < 12) ? a : NEG; idx = (lane < 12) ? lane : 64;
    #pragma unroll
    for (int off = 16; off; off >>= 1) {
        float ov = __shfl_xor_sync(FULL, v, off);
        int   oi = __shfl_xor_sync(FULL, idx, off);
        if (ov > v || (ov == v && oi < idx)) { v = ov; idx = oi; }
    }
    const int x_bin = idx;

    // z_bin = argmax reg[12:24]
    v = (lane >= 12 && lane < 24) ? a : NEG;
    idx = (lane >= 12 && lane < 24) ? (lane - 12) : 64;
    #pragma unroll
    for (int off = 16; off; off >>= 1) {
        float ov = __shfl_xor_sync(FULL, v, off);
        int   oi = __shfl_xor_sync(FULL, idx, off);
        if (ov > v || (ov == v && oi < idx)) { v = ov; idx = oi; }
    }
    const int z_bin = idx;

    // ry_bin = argmax reg[49:61] -> bv lanes 17..28
    v = (lane >= 17 && lane < 29) ? bv : NEG;
    idx = (lane >= 17 && lane < 29) ? (lane - 17) : 64;
    #pragma unroll
    for (int off = 16; off; off >>= 1) {
        float ov = __shfl_xor_sync(FULL, v, off);
        int   oi = __shfl_xor_sync(FULL, idx, off);
        if (ov > v || (ov == v && oi < idx)) { v = ov; idx = oi; }
    }
    const int ry_bin = idx;

    // gathers (x_bin/z_bin/ry_bin are warp-uniform)
    const float x_res  = (x_bin < 8)  ? __shfl_sync(FULL, a,  24 + x_bin)
                                      : __shfl_sync(FULL, bv, x_bin - 8);      // reg[24 + x_bin]
    const float z_res  = __shfl_sync(FULL, bv, 4 + z_bin);                     // reg[36 + z_bin]
    const float y_off  = __shfl_sync(FULL, bv, 16);                            // reg[48]
    const float ry_res = (ry_bin < 3) ? __shfl_sync(FULL, bv, 29 + ry_bin)
                                      : __shfl_sync(FULL, cv, ry_bin - 3);     // reg[61 + ry_bin]
    const float hr = __shfl_sync(FULL, cv, 9);                                 // reg[73]
    const float wr = __shfl_sync(FULL, cv, 10);                                // reg[74]
    const float lr = __shfl_sync(FULL, cv, 11);                                // reg[75]

    // roi (xyz)
    const float roiv = (lane < 3) ? xyz[(size_t)gw * 3 + lane] : 0.f;
    const float roi0 = __shfl_sync(FULL, roiv, 0);
    const float roi1 = __shfl_sync(FULL, roiv, 1);
    const float roi2 = __shfl_sync(FULL, roiv, 2);

    const float an0 = __ldg(anchor);
    const float an1 = __ldg(anchor + 1);
    const float an2 = __ldg(anchor + 2);

    // decode
    const float LOC_BIN = 0.5f, HALF = 0.25f, SCOPE = 3.0f;
    float pos_x = (float)x_bin * LOC_BIN + HALF - SCOPE + x_res * LOC_BIN;
    float pos_z = (float)z_bin * LOC_BIN + HALF - SCOPE + z_res * LOC_BIN;
    float pos_y = roi1 + y_off;

    const float TWO_PI = 6.28318530717958647692f;
    const float PI_    = 3.14159265358979323846f;
    const float APC    = 0.52359877559829887308f;   // 2*pi/12
    float ry = (float)ry_bin * APC + ry_res * (APC * 0.5f);
    ry = fmodf(ry, TWO_PI);
    if (ry < 0.f) ry += TWO_PI;        // python-mod semantics (sign of divisor)
    if (ry > PI_) ry -= TWO_PI;

    const float h_ = hr * an0 + an0;
    const float w_ = wr * an1 + an1;
    const float l_ = lr * an2 + an2;

    const float px = pos_x + roi0;
    const float pz = pos_z + roi2;
    const float py = pos_y + h_ * 0.5f;   // post_process: lift to top center

    const float sc = __ldg(scores + gw);  // broadcast within warp

    if (lane == 0) {
        float4* pp = (float4*)g_props;
        pp[2 * (size_t)gw]     = make_float4(px, py, pz, h_);
        pp[2 * (size_t)gw + 1] = make_float4(w_, l_, ry, sc);

        // composite sort key: (row, descending-score) ascending; radix sort is
        // stable -> equal scores keep original index order (matches jnp.argsort)
        unsigned int u = __float_as_uint(sc);
        u ^= (u & 0x80000000u) ? 0xFFFFFFFFu : 0x80000000u;   // float -> ascending-sortable
        const unsigned int key32 = ~u;                         // descending score
        g_keys[gw] = ((unsigned long long)(gw >> 17) << 32) | (unsigned long long)key32;
        g_vals[gw] = (unsigned int)gw;
    }
}

// ---------------- gather sorted proposals ----------------
__global__ void gather_kernel(const unsigned int* __restrict__ order,
                              float4* __restrict__ out)
{
    const int i = blockIdx.x * blockDim.x + threadIdx.x;
    if (i >= M_) return;
    const unsigned int s = order[i];
    const float4* pp = (const float4*)g_props;
    out[2 * (size_t)i]     = __ldg(&pp[2 * (size_t)s]);
    out[2 * (size_t)i + 1] = __ldg(&pp[2 * (size_t)s + 1]);
}

// ---------------- launch ----------------
extern "C" void kernel_launch(void* const* d_in, const int* in_sizes, int n_in,
                              void* d_out, int out_size)
{
    const float* scores = (const float*)d_in[0];
    const float* reg    = (const float*)d_in[1];
    const float* xyz    = (const float*)d_in[2];
    const float* anchor = (const float*)d_in[3];

    // 8 warps / block, one warp per point
    decode_kernel<<<M_ / 8, 256>>>(scores, reg, xyz, anchor);

    void *pk, *pka, *pv, *pva, *pt;
    cudaGetSymbolAddress(&pk,  g_keys);
    cudaGetSymbolAddress(&pka, g_keys_alt);
    cudaGetSymbolAddress(&pv,  g_vals);
    cudaGetSymbolAddress(&pva, g_vals_alt);
    cudaGetSymbolAddress(&pt,  g_temp);

    size_t tb = sizeof(g_temp);
    // stable LSD radix over bits [0, 35): 32 score bits + 3 row bits
    cub::DeviceRadixSort::SortPairs(pt, tb,
        (const unsigned long long*)pk, (unsigned long long*)pka,
        (const unsigned int*)pv, (unsigned int*)pva,
        M_, 0, 35);

    gather_kernel<<<(M_ + 255) / 256, 256>>>((const unsigned int*)pva, (float4*)d_out);
}

// round 2
// speedup vs baseline: 1.9351x; 1.9351x over previous
#include <cuda_runtime.h>
#include <cstdint>
#include <cub/cub.cuh>

// Problem constants (from reference setup_inputs)
#define B_  8
#define N_  131072            // 2^17
#define M_  (B_ * N_)         // 1048576 points
#define C_  76
#define PTS 128               // points per decode block

// ---------------- device scratch (no allocation allowed) ----------------
__device__ float               g_props[(size_t)M_ * 8];   // 32 MB  [x, ytop, z, h, w, l, ry, score]
__device__ unsigned long long  g_keys[M_];                // 8 MB
__device__ unsigned long long  g_keys_alt[M_];            // 8 MB
__device__ unsigned int        g_vals[M_];                // 4 MB
__device__ unsigned int        g_vals_alt[M_];            // 4 MB
__device__ unsigned char       g_temp[32u << 20];         // 32 MB cub temp

// ---------------- decode: thread per point, smem-staged ----------------
// reg layout per point (76 floats):
//  [0:12)  x bins     [12:24) z bins    [24:36) x res    [36:48) z res
//  [48]    y offset   [49:61) ry bins   [61:73) ry res   [73:76) hwl
__global__ __launch_bounds__(PTS) void decode_kernel(
    const float* __restrict__ scores,
    const float* __restrict__ reg,
    const float* __restrict__ xyz,
    const float* __restrict__ anchor)
{
    __shared__ float s[PTS * 77];        // pad 76->77: conflict-free row access
    __shared__ float sxyz[PTS * 3];

    const int tid  = threadIdx.x;
    const int base = blockIdx.x * PTS;   // first point of this block

    // cooperative coalesced load of PTS*76 floats -> padded smem
    const float* gsrc = reg + (size_t)base * C_;
    #pragma unroll
    for (int k = 0; k < C_; ++k) {
        const int i = tid + k * PTS;     // 0 .. PTS*76-1
        const int p = i / C_;
        const int c = i - p * C_;
        s[p * 77 + c] = gsrc[i];
    }
    #pragma unroll
    for (int k = 0; k < 3; ++k)
        sxyz[tid + k * PTS] = xyz[(size_t)base * 3 + tid + k * PTS];
    __syncthreads();

    const int   p  = base + tid;
    const float* r = s + tid * 77;

    // serial argmaxes (first-max tiebreak == jnp.argmax)
    int xb = 0; float xv = r[0];
    #pragma unroll
    for (int j = 1; j < 12; ++j) { float v = r[j];      if (v > xv) { xv = v; xb = j; } }
    int zb = 0; float zv = r[12];
    #pragma unroll
    for (int j = 1; j < 12; ++j) { float v = r[12 + j]; if (v > zv) { zv = v; zb = j; } }
    int rb = 0; float rv = r[49];
    #pragma unroll
    for (int j = 1; j < 12; ++j) { float v = r[49 + j]; if (v > rv) { rv = v; rb = j; } }

    const float x_res  = r[24 + xb];
    const float z_res  = r[36 + zb];
    const float y_off  = r[48];
    const float ry_res = r[61 + rb];
    const float hr = r[73], wr = r[74], lr = r[75];

    const float roi0 = sxyz[tid * 3 + 0];
    const float roi1 = sxyz[tid * 3 + 1];
    const float roi2 = sxyz[tid * 3 + 2];

    const float an0 = __ldg(anchor);
    const float an1 = __ldg(anchor + 1);
    const float an2 = __ldg(anchor + 2);

    // decode
    const float LOC_BIN = 0.5f, HALF = 0.25f, SCOPE = 3.0f;
    const float pos_x = (float)xb * LOC_BIN + HALF - SCOPE + x_res * LOC_BIN;
    const float pos_z = (float)zb * LOC_BIN + HALF - SCOPE + z_res * LOC_BIN;
    const float pos_y = roi1 + y_off;

    const float TWO_PI = 6.28318530717958647692f;
    const float PI_    = 3.14159265358979323846f;
    const float APC    = 0.52359877559829887308f;   // 2*pi/12
    float ry = (float)rb * APC + ry_res * (APC * 0.5f);
    ry = fmodf(ry, TWO_PI);
    if (ry < 0.f) ry += TWO_PI;        // python-mod semantics
    if (ry > PI_) ry -= TWO_PI;

    const float h_ = hr * an0 + an0;
    const float w_ = wr * an1 + an1;
    const float l_ = lr * an2 + an2;

    const float px = pos_x + roi0;
    const float pz = pos_z + roi2;
    const float py = pos_y + h_ * 0.5f;   // post_process: lift to top center

    const float sc = __ldg(scores + p);

    float4* pp = (float4*)g_props;
    pp[2 * (size_t)p]     = make_float4(px, py, pz, h_);
    pp[2 * (size_t)p + 1] = make_float4(w_, l_, ry, sc);

    // composite sort key: (row, descending-score); radix sort is stable ->
    // ties keep original index order (matches jnp.argsort on -scores)
    unsigned int u = __float_as_uint(sc);
    u ^= (u & 0x80000000u) ? 0xFFFFFFFFu : 0x80000000u;   // float -> sortable
    const unsigned int key32 = ~u;                         // descending score
    g_keys[p] = ((unsigned long long)(p >> 17) << 32) | (unsigned long long)key32;
    g_vals[p] = (unsigned int)p;
}

// ---------------- gather sorted proposals ----------------
__global__ void gather_kernel(const unsigned int* __restrict__ order,
                              float4* __restrict__ out)
{
    const int i = blockIdx.x * blockDim.x + threadIdx.x;
    if (i >= M_) return;
    const unsigned int sidx = order[i];
    const float4* pp = (const float4*)g_props;
    out[2 * (size_t)i]     = __ldg(&pp[2 * (size_t)sidx]);
    out[2 * (size_t)i + 1] = __ldg(&pp[2 * (size_t)sidx + 1]);
}

// ---------------- launch ----------------
extern "C" void kernel_launch(void* const* d_in, const int* in_sizes, int n_in,
                              void* d_out, int out_size)
{
    const float* scores = (const float*)d_in[0];
    const float* reg    = (const float*)d_in[1];
    const float* xyz    = (const float*)d_in[2];
    const float* anchor = (const float*)d_in[3];

    decode_kernel<<<M_ / PTS, PTS>>>(scores, reg, xyz, anchor);

    void *pk, *pka, *pv, *pva, *pt;
    cudaGetSymbolAddress(&pk,  g_keys);
    cudaGetSymbolAddress(&pka, g_keys_alt);
    cudaGetSymbolAddress(&pv,  g_vals);
    cudaGetSymbolAddress(&pva, g_vals_alt);
    cudaGetSymbolAddress(&pt,  g_temp);

    size_t tb = sizeof(g_temp);
    // stable LSD radix over bits [0, 35): 32 score bits + 3 row bits
    cub::DeviceRadixSort::SortPairs(pt, tb,
        (const unsigned long long*)pk, (unsigned long long*)pka,
        (const unsigned int*)pv, (unsigned int*)pva,
        M_, 0, 35);

    gather_kernel<<<(M_ + 255) / 256, 256>>>((const unsigned int*)pva, (float4*)d_out);
}

// round 3
// speedup vs baseline: 1.9968x; 1.0319x over previous
#include <cuda_runtime.h>
#include <cstdint>
#include <cub/cub.cuh>

// Problem constants (from reference setup_inputs)
#define B_  8
#define N_  131072            // 2^17
#define M_  (B_ * N_)         // 1048576 points
#define C_  76
#define PTS 128               // points per decode block

// rank+gather tiling
#define GTH    256            // threads per rank/gather block
#define GIT    8              // items per thread
#define GTILE  (GTH * GIT)    // 2048 items per tile
#define NTILES (M_ / GTILE)   // 512

#define FLAG_AGG (1u << 30)
#define FLAG_INC (2u << 30)
#define VALMASK  ((1u << 30) - 1u)

// ---------------- device scratch (no allocation allowed) ----------------
__device__ float               g_props[(size_t)M_ * 8];   // 32 MB
__device__ unsigned int        g_keys[M_];                // 4 MB (32-bit keys)
__device__ unsigned int        g_keys_alt[M_];            // 4 MB
__device__ unsigned int        g_vals[M_];                // 4 MB
__device__ unsigned int        g_vals_alt[M_];            // 4 MB
__device__ unsigned char       g_temp[32u << 20];         // 32 MB cub temp
__device__ unsigned int        g_tile_counter;            // dynamic tile ids
__device__ unsigned int        g_tile_status[NTILES][8];  // lookback state

// ---------------- decode: thread per point, smem-staged ----------------
// reg layout per point (76 floats):
//  [0:12)  x bins     [12:24) z bins    [24:36) x res    [36:48) z res
//  [48]    y offset   [49:61) ry bins   [61:73) ry res   [73:76) hwl
__global__ __launch_bounds__(PTS) void decode_kernel(
    const float* __restrict__ scores,
    const float* __restrict__ reg,
    const float* __restrict__ xyz,
    const float* __restrict__ anchor)
{
    __shared__ float s[PTS * 77];        // pad 76->77: conflict-free row access
    __shared__ float sxyz[PTS * 3];

    const int tid  = threadIdx.x;
    const int base = blockIdx.x * PTS;

    const float* gsrc = reg + (size_t)base * C_;
    #pragma unroll
    for (int k = 0; k < C_; ++k) {
        const int i = tid + k * PTS;
        const int p = i / C_;
        const int c = i - p * C_;
        s[p * 77 + c] = gsrc[i];
    }
    #pragma unroll
    for (int k = 0; k < 3; ++k)
        sxyz[tid + k * PTS] = xyz[(size_t)base * 3 + tid + k * PTS];
    __syncthreads();

    const int    p = base + tid;
    const float* r = s + tid * 77;

    int xb = 0; float xv = r[0];
    #pragma unroll
    for (int j = 1; j < 12; ++j) { float v = r[j];      if (v > xv) { xv = v; xb = j; } }
    int zb = 0; float zv = r[12];
    #pragma unroll
    for (int j = 1; j < 12; ++j) { float v = r[12 + j]; if (v > zv) { zv = v; zb = j; } }
    int rb = 0; float rv = r[49];
    #pragma unroll
    for (int j = 1; j < 12; ++j) { float v = r[49 + j]; if (v > rv) { rv = v; rb = j; } }

    const float x_res  = r[24 + xb];
    const float z_res  = r[36 + zb];
    const float y_off  = r[48];
    const float ry_res = r[61 + rb];
    const float hr = r[73], wr = r[74], lr = r[75];

    const float roi0 = sxyz[tid * 3 + 0];
    const float roi1 = sxyz[tid * 3 + 1];
    const float roi2 = sxyz[tid * 3 + 2];

    const float an0 = __ldg(anchor);
    const float an1 = __ldg(anchor + 1);
    const float an2 = __ldg(anchor + 2);

    const float LOC_BIN = 0.5f, HALF = 0.25f, SCOPE = 3.0f;
    const float pos_x = (float)xb * LOC_BIN + HALF - SCOPE + x_res * LOC_BIN;
    const float pos_z = (float)zb * LOC_BIN + HALF - SCOPE + z_res * LOC_BIN;
    const float pos_y = roi1 + y_off;

    const float TWO_PI = 6.28318530717958647692f;
    const float PI_    = 3.14159265358979323846f;
    const float APC    = 0.52359877559829887308f;   // 2*pi/12
    float ry = (float)rb * APC + ry_res * (APC * 0.5f);
    ry = fmodf(ry, TWO_PI);
    if (ry < 0.f) ry += TWO_PI;
    if (ry > PI_) ry -= TWO_PI;

    const float h_ = hr * an0 + an0;
    const float w_ = wr * an1 + an1;
    const float l_ = lr * an2 + an2;

    const float px = pos_x + roi0;
    const float pz = pos_z + roi2;
    const float py = pos_y + h_ * 0.5f;

    const float sc = __ldg(scores + p);

    float4* pp = (float4*)g_props;
    pp[2 * (size_t)p]     = make_float4(px, py, pz, h_);
    pp[2 * (size_t)p + 1] = make_float4(w_, l_, ry, sc);

    // 32-bit sortable key: ascending == descending score. Stable radix keeps
    // original index order for ties => per-row order matches jnp.argsort.
    unsigned int u = __float_as_uint(sc);
    u ^= (u & 0x80000000u) ? 0xFFFFFFFFu : 0x80000000u;
    g_keys[p] = ~u;
    g_vals[p] = (unsigned int)p;
}

// ------- fused stable 8-way rank (decoupled lookback) + gather/scatter -------
// Input: vals sorted by descending score (rows interleaved). For each element,
// rank within its row among earlier sorted positions; write prop row to
// out[row*N + rank]. This replaces the 5th radix pass AND the gather kernel.
__global__ __launch_bounds__(GTH) void rank_gather_kernel(
    const unsigned int* __restrict__ sorted_vals,
    float4* __restrict__ out)
{
    __shared__ unsigned int s_warpcnt[8][8];   // [warp][row]
    __shared__ unsigned int s_base[8];         // running per-row intra-tile base
    __shared__ unsigned int s_excl[8];         // exclusive prefix from lookback
    __shared__ unsigned int s_tile;

    const int tid  = threadIdx.x;
    const int lane = tid & 31;
    const int warp = tid >> 5;
    const unsigned FULL = 0xffffffffu;

    if (tid == 0) s_tile = atomicAdd(&g_tile_counter, 1u);
    if (tid < 8)  s_base[tid] = 0;
    __syncthreads();
    const int tile = (int)s_tile;
    const int ibase = tile * GTILE;

    unsigned int v[GIT];  int row[GIT];  unsigned int rk[GIT];
    #pragma unroll
    for (int k = 0; k < GIT; ++k) {
        v[k]   = __ldg(sorted_vals + ibase + k * GTH + tid);  // striped: global order
        row[k] = (int)(v[k] >> 17);
    }

    // sequential slices: stable intra-tile multisplit rank
    #pragma unroll
    for (int k = 0; k < GIT; ++k) {
        unsigned int bal[8];
        #pragma unroll
        for (int r = 0; r < 8; ++r) bal[r] = __ballot_sync(FULL, row[k] == r);
        const unsigned int lt = (1u << lane) - 1u;
        unsigned int rank = __popc(bal[row[k]] & lt);
        if (lane < 8) s_warpcnt[warp][lane] = __popc(bal[lane]);
        __syncthreads();
        unsigned int off = s_base[row[k]];
        #pragma unroll
        for (int w = 0; w < 8; ++w)
            if (w < warp) off += s_warpcnt[w][row[k]];
        rk[k] = off + rank;
        __syncthreads();
        if (tid < 8) {
            unsigned int t = 0;
            #pragma unroll
            for (int w = 0; w < 8; ++w) t += s_warpcnt[w][tid];
            s_base[tid] += t;
        }
        __syncthreads();
    }

    // publish aggregate + decoupled lookback (single-word flag|count protocol)
    if (tid < 8) {
        const unsigned int agg = s_base[tid];
        volatile unsigned int* st_col = &g_tile_status[0][tid];
        if (tile == 0) {
            g_tile_status[0][tid] = FLAG_INC | agg;
            __threadfence();
            s_excl[tid] = 0;
        } else {
            g_tile_status[tile][tid] = FLAG_AGG | agg;
            __threadfence();
            unsigned int excl = 0;
            int t = tile - 1;
            while (true) {
                unsigned int stv;
                do { stv = st_col[(size_t)t * 8]; } while (stv == 0u);
                excl += stv & VALMASK;
                if (stv & FLAG_INC) break;
                --t;
            }
            g_tile_status[tile][tid] = FLAG_INC | (excl + agg);
            __threadfence();
            s_excl[tid] = excl;
        }
    }
    __syncthreads();

    const float4* pp = (const float4*)g_props;
    #pragma unroll
    for (int k = 0; k < GIT; ++k) {
        const unsigned int src = v[k];
        const unsigned int dst = (unsigned int)row[k] * N_ + s_excl[row[k]] + rk[k];
        out[2 * (size_t)dst]     = __ldg(&pp[2 * (size_t)src]);
        out[2 * (size_t)dst + 1] = __ldg(&pp[2 * (size_t)src + 1]);
    }
}

// ---------------- launch ----------------
extern "C" void kernel_launch(void* const* d_in, const int* in_sizes, int n_in,
                              void* d_out, int out_size)
{
    const float* scores = (const float*)d_in[0];
    const float* reg    = (const float*)d_in[1];
    const float* xyz    = (const float*)d_in[2];
    const float* anchor = (const float*)d_in[3];

    // reset lookback state each launch (graph-capturable memset nodes)
    void *pc, *ps;
    cudaGetSymbolAddress(&pc, g_tile_counter);
    cudaGetSymbolAddress(&ps, g_tile_status);
    cudaMemsetAsync(pc, 0, sizeof(unsigned int));
    cudaMemsetAsync(ps, 0, sizeof(unsigned int) * NTILES * 8);

    decode_kernel<<<M_ / PTS, PTS>>>(scores, reg, xyz, anchor);

    void *pk, *pka, *pv, *pva, *pt;
    cudaGetSymbolAddress(&pk,  g_keys);
    cudaGetSymbolAddress(&pka, g_keys_alt);
    cudaGetSymbolAddress(&pv,  g_vals);
    cudaGetSymbolAddress(&pva, g_vals_alt);
    cudaGetSymbolAddress(&pt,  g_temp);

    size_t tb = sizeof(g_temp);
    // stable LSD radix, 32-bit keys => 4 onesweep passes
    cub::DeviceRadixSort::SortPairs(pt, tb,
        (const unsigned int*)pk, (unsigned int*)pka,
        (const unsigned int*)pv, (unsigned int*)pva,
        M_, 0, 32);

    rank_gather_kernel<<<NTILES, GTH>>>((const unsigned int*)pva, (float4*)d_out);
}